// round 1
// baseline (speedup 1.0000x reference)
#include <cuda_runtime.h>
#include <cstdint>

#define LOG2E 1.4426950408889634f

// ---------------- scratch (device globals: allocation-free rule) ----------------
// Wh laid out as [b][n][h*32+d]  (i.e. nf @ concat(W_h) row-major 8192 x 256)
__device__ float g_Wh[8 * 1024 * 256];     // 8 MB
__device__ float g_e1[8 * 8 * 1024];       // [bh][n]
__device__ float g_e2[8 * 8 * 1024];       // [bh][n]
__device__ float g_maxe2[64];              // per (b,h)

// ---------------- f32x2 helpers ----------------
__device__ __forceinline__ unsigned long long pk2(float lo, float hi) {
    unsigned long long r;
    asm("mov.b64 %0, {%1,%2};" : "=l"(r) : "f"(lo), "f"(hi));
    return r;
}
__device__ __forceinline__ void upk2(unsigned long long v, float& lo, float& hi) {
    asm("mov.b64 {%0,%1}, %2;" : "=f"(lo), "=f"(hi) : "l"(v));
}
__device__ __forceinline__ void fma2(unsigned long long& d, unsigned long long a,
                                     unsigned long long b) {
    asm("fma.rn.f32x2 %0, %1, %2, %0;" : "+l"(d) : "l"(a), "l"(b));
}
__device__ __forceinline__ unsigned long long add2(unsigned long long a,
                                                   unsigned long long b) {
    unsigned long long r;
    asm("add.rn.f32x2 %0, %1, %2;" : "=l"(r) : "l"(a), "l"(b));
    return r;
}

// ---------------- kernel 1: Wh = nf(8192x256) @ Wcat(256x256) ----------------
// Wcat[k][c] = W[c>>5][k][c&31], W layout (H, 256, 32)
__global__ void gemm_wh_kernel(const float* __restrict__ A, const float* __restrict__ Wm) {
    __shared__ __align__(16) float as[16][68];  // pad to avoid STS conflicts, 16B-aligned rows
    __shared__ __align__(16) float bs[16][64];

    const int row0 = blockIdx.x * 64;
    const int col0 = blockIdx.y * 64;
    const int t = threadIdx.x;
    const int tx = t & 15;   // col group
    const int ty = t >> 4;   // row group

    float acc[4][4];
#pragma unroll
    for (int r = 0; r < 4; r++)
#pragma unroll
        for (int c = 0; c < 4; c++) acc[r][c] = 0.0f;

    for (int k0 = 0; k0 < 256; k0 += 16) {
#pragma unroll
        for (int l = 0; l < 4; l++) {
            int e = t + l * 256;
            int r = e >> 4, kk = e & 15;
            as[kk][r] = A[(size_t)(row0 + r) * 256 + k0 + kk];
        }
#pragma unroll
        for (int l = 0; l < 4; l++) {
            int e = t + l * 256;
            int c = e & 63, kk = e >> 6;
            int col = col0 + c;
            bs[kk][c] = Wm[(size_t)(col >> 5) * 8192 + (size_t)(k0 + kk) * 32 + (col & 31)];
        }
        __syncthreads();
#pragma unroll
        for (int kk = 0; kk < 16; kk++) {
            float4 a4 = *(const float4*)&as[kk][ty << 2];
            float4 b4 = *(const float4*)&bs[kk][tx << 2];
            float av[4] = {a4.x, a4.y, a4.z, a4.w};
            float bv[4] = {b4.x, b4.y, b4.z, b4.w};
#pragma unroll
            for (int r = 0; r < 4; r++)
#pragma unroll
                for (int c = 0; c < 4; c++) acc[r][c] = fmaf(av[r], bv[c], acc[r][c]);
        }
        __syncthreads();
    }
#pragma unroll
    for (int r = 0; r < 4; r++) {
        float4 o = make_float4(acc[r][0], acc[r][1], acc[r][2], acc[r][3]);
        *(float4*)&g_Wh[(size_t)(row0 + (ty << 2) + r) * 256 + col0 + (tx << 2)] = o;
    }
}

// ---------------- kernel 2: e1, e2, max(e2) per (b,h) ----------------
__global__ void compute_e_kernel(const float* __restrict__ a) {
    const int bh = blockIdx.x;
    const int b = bh >> 3, h = bh & 7;
    const int tid = threadIdx.x;
    const int warp = tid >> 5, lane = tid & 31;

    const float a1v = a[h * 64 + lane];
    const float a2v = a[h * 64 + 32 + lane];
    __shared__ float wmax[8];

    const float* base = g_Wh + (size_t)(b * 1024) * 256 + h * 32;
    float mx = -1e30f;

    for (int nn = 0; nn < 128; nn++) {
        int n = warp * 128 + nn;
        float wh = base[(size_t)n * 256 + lane];
        float x = wh * a1v;
        float y = wh * a2v;
#pragma unroll
        for (int s = 16; s >= 1; s >>= 1) {
            x += __shfl_xor_sync(0xffffffffu, x, s);
            y += __shfl_xor_sync(0xffffffffu, y, s);
        }
        if (lane == 0) {
            g_e1[bh * 1024 + n] = x;
            g_e2[bh * 1024 + n] = y;
        }
        mx = fmaxf(mx, y);
    }
    if (lane == 0) wmax[warp] = mx;
    __syncthreads();
    if (tid == 0) {
        float m = wmax[0];
#pragma unroll
        for (int w = 1; w < 8; w++) m = fmaxf(m, wmax[w]);
        g_maxe2[bh] = m;
    }
}

// ---------------- kernel 3: fused masked softmax + P @ Wh + bias + relu ----------------
// grid: 128 CTAs = 64 (b,h) pairs x 2 halves of i-rows. block = 512 (16 warps).
// smem: Wh slice of this (b,h) [1024x32] = 128KB, e2 row 4KB, p-buffers 2KB/warp.
#define ATTN_SMEM ((32768 + 1024 + 16 * 512) * 4)

__global__ void __launch_bounds__(512, 1)
gat_attn_kernel(const int* __restrict__ adj, const float* __restrict__ bias,
                float* __restrict__ out) {
    extern __shared__ __align__(16) float smem[];
    float* whs = smem;                   // 32768 floats
    float* e2s = smem + 32768;           // 1024 floats
    float* pbuf = smem + 32768 + 1024;   // 16 * 512 floats

    const int bh = blockIdx.x >> 1;
    const int hv = blockIdx.x & 1;       // which half of the 1024 i-rows
    const int b = bh >> 3, h = bh & 7;
    const int tid = threadIdx.x;

    // stage Wh slice (all 1024 j-rows, 32 dims of this head), coalesced
    const float4* gbase = (const float4*)(g_Wh) + ((size_t)b * 1024 * 256 + h * 32) / 4;
    float4* whs4 = (float4*)whs;
    for (int f = tid; f < 8192; f += 512) {
        int j = f >> 3, q = f & 7;
        whs4[f] = gbase[(size_t)j * 64 + q];
    }
    for (int n = tid; n < 1024; n += 512) e2s[n] = g_e2[bh * 1024 + n];
    __syncthreads();

    const float maxe2 = g_maxe2[bh];
    const int warp = tid >> 5, lane = tid & 31;
    const int dg = lane & 7, jjq = lane >> 3;
    float4* pw4 = (float4*)(pbuf + warp * 512);
    const float* e1p = g_e1 + bh * 1024;
    const float4 bias4 = ((const float4*)(bias + h * 32))[dg];

    for (int grp = 0; grp < 8; grp++) {
        const int i0 = hv * 512 + ((grp * 16 + warp) << 2);  // 4-row group
        const int* adjrow = adj + (size_t)(b * 1024 + i0) * 1024;

        float e1v[4], mneg[4];
#pragma unroll
        for (int r = 0; r < 4; r++) {
            float e = e1p[i0 + r];
            e1v[r] = e;
            float s = e + maxe2;
            s = fmaxf(s, 0.2f * s);          // leaky upper bound: m_i >= all scores
            mneg[r] = -s * LOG2E;
        }

        unsigned long long acc[4][2];
#pragma unroll
        for (int r = 0; r < 4; r++) { acc[r][0] = 0ull; acc[r][1] = 0ull; }
        float sums[4] = {0.f, 0.f, 0.f, 0.f};

        for (int c0 = 0; c0 < 1024; c0 += 128) {
            // ---- sub-phase A: scores + exp for 128 j, 4 rows (lane = j-lane) ----
#pragma unroll
            for (int g = 0; g < 4; g++) {
                int j = c0 + (g << 5) + lane;
                float ej = e2s[j];
                float pq[4];
#pragma unroll
                for (int r = 0; r < 4; r++) {
                    int am = adjrow[r * 1024 + j];
                    float s = e1v[r] + ej;
                    s = fmaxf(s, 0.2f * s);
                    float arg = am ? fmaf(s, LOG2E, mneg[r]) : -10000.0f;
                    float p = exp2f(arg);
                    sums[r] += p;
                    pq[r] = p;
                }
                pw4[(g << 5) + lane] = make_float4(pq[0], pq[1], pq[2], pq[3]);
            }
            __syncwarp();

            // ---- sub-phase B: acc += P * Wh   (lane = jj*8 + dg) ----
            const float4* wrow = whs4 + ((size_t)c0 << 3);
#pragma unroll 8
            for (int blk = 0; blk < 32; blk++) {
                float4 p4 = pw4[(blk << 2) + jjq];          // p for rows 0..3 at j = c0+blk*4+jjq
                float4 w = wrow[(blk << 5) + lane];         // Wh[j][dg*4 .. +3]
                unsigned long long wlo = pk2(w.x, w.y);
                unsigned long long whi = pk2(w.z, w.w);
                unsigned long long pp;
                pp = pk2(p4.x, p4.x); fma2(acc[0][0], wlo, pp); fma2(acc[0][1], whi, pp);
                pp = pk2(p4.y, p4.y); fma2(acc[1][0], wlo, pp); fma2(acc[1][1], whi, pp);
                pp = pk2(p4.z, p4.z); fma2(acc[2][0], wlo, pp); fma2(acc[2][1], whi, pp);
                pp = pk2(p4.w, p4.w); fma2(acc[3][0], wlo, pp); fma2(acc[3][1], whi, pp);
            }
            __syncwarp();
        }

        // ---- reduce partial accs over the 4 jj-lanes sharing each dg ----
#pragma unroll
        for (int r = 0; r < 4; r++)
#pragma unroll
            for (int pi = 0; pi < 2; pi++) {
                acc[r][pi] = add2(acc[r][pi], __shfl_xor_sync(0xffffffffu, acc[r][pi], 8));
                acc[r][pi] = add2(acc[r][pi], __shfl_xor_sync(0xffffffffu, acc[r][pi], 16));
            }
        // ---- reduce sums over all 32 j-lanes ----
#pragma unroll
        for (int r = 0; r < 4; r++) {
            float s = sums[r];
#pragma unroll
            for (int m = 16; m >= 1; m >>= 1) s += __shfl_xor_sync(0xffffffffu, s, m);
            sums[r] = s;
        }

        // ---- epilogue: normalize, +bias, relu, store (lanes 0..7 store) ----
#pragma unroll
        for (int r = 0; r < 4; r++) {
            float inv = 1.0f / sums[r];
            float f0, f1, f2, f3;
            upk2(acc[r][0], f0, f1);
            upk2(acc[r][1], f2, f3);
            float4 o;
            o.x = fmaxf(fmaf(f0, inv, bias4.x), 0.0f);
            o.y = fmaxf(fmaf(f1, inv, bias4.y), 0.0f);
            o.z = fmaxf(fmaf(f2, inv, bias4.z), 0.0f);
            o.w = fmaxf(fmaf(f3, inv, bias4.w), 0.0f);
            if (jjq == 0) {
                *(float4*)(out + (size_t)((b << 10) + i0 + r) * 256 + (h << 5) + (dg << 2)) = o;
            }
        }
    }
}

// ---------------- launch ----------------
extern "C" void kernel_launch(void* const* d_in, const int* in_sizes, int n_in,
                              void* d_out, int out_size) {
    const float* nf   = (const float*)d_in[0];
    const int*   adj  = (const int*)d_in[1];
    const float* Wm   = (const float*)d_in[2];
    const float* av   = (const float*)d_in[3];
    const float* bias = (const float*)d_in[4];
    float* out = (float*)d_out;

    gemm_wh_kernel<<<dim3(128, 4, 1), 256>>>(nf, Wm);
    compute_e_kernel<<<64, 256>>>(av);
    cudaFuncSetAttribute(gat_attn_kernel,
                         cudaFuncAttributeMaxDynamicSharedMemorySize, ATTN_SMEM);
    gat_attn_kernel<<<128, 512, ATTN_SMEM>>>(adj, bias, out);
}